// round 9
// baseline (speedup 1.0000x reference)
#include <cuda_runtime.h>

// ---------------- problem constants ----------------
#define BATCH 128
#define CIN   500
#define HIN   16
#define WIN   16
#define NPIX  (BATCH*HIN*WIN)     // 32768
#define KTOP  30

#define C1 300
#define O1 34
#define C2 100
#define O2 36
#define C3 3
#define O3 38

// k_tail: 148 blocks x 512 threads, 1 block/SM -> co-resident, cheap barrier
#define TB_NB 148
#define TB_NT 512
#define NTHREADS (TB_NB*TB_NT)    // 75776
#define NWARPS (NTHREADS/32)      // 2368

#define NT 256
#define NFT 256000                // flag threads: 1000 blocks x 256
#define N4 (BATCH*CIN*HIN*WIN/4)  // 4,096,000 float4 = 16 * NFT exactly

// ---------------- static device scratch (zero at module load; self-cleaned) --
__device__ float g_l1[CIN];
__device__ float g_thr[CIN];
__device__ int   g_flagd[NPIX];
__device__ int   g_cand[NPIX];
__device__ int   g_ncand;
__device__ int   g_cnt[NPIX];
__device__ int   g_chid[NPIX*KTOP];
__device__ float g_qval[NPIX*KTOP];

__device__ int   g_dirty1[BATCH*O1*O1];
__device__ int   g_dirty2[BATCH*O2*O2];
__device__ int   g_dirty3[BATCH*O3*O3];
__device__ int   g_list1[BATCH*O1*O1];
__device__ int   g_list2[BATCH*O2*O2];
__device__ int   g_n1, g_n2;

__device__ float g_delta1[BATCH*C1*O1*O1];
__device__ float g_delta2[BATCH*C2*O2*O2];

__device__ float g_base2cls[25*C2];
__device__ float g_base3[C3*O3*O3];

__device__ int g_thr_ready;       // 16 producer blocks; reset by k_tail
__device__ int g_b2_ready;        // 1 producer block;  reset by k_tail
__device__ unsigned g_bar[8];     // packed count[0:12)/gen[12:32), monotonic

// ---------------- helpers ----------------
__device__ __forceinline__ float sgnf(float a) {
    return (float)((a > 0.f) - (a < 0.f));
}
__device__ __forceinline__ int warp_sum(int v) {
    #pragma unroll
    for (int o = 16; o > 0; o >>= 1) v += __shfl_xor_sync(0xffffffffu, v, o);
    return v;
}
__device__ __forceinline__ int cls36(int q) {
    return (q == 0) ? 0 : (q == 1) ? 1 : (q <= 33) ? 2 : (q == 34) ? 3 : 4;
}
__device__ __forceinline__ void grid_bar(int slot) {
    __syncthreads();
    if (threadIdx.x == 0) {
        __threadfence();
        unsigned old = atomicAdd(&g_bar[slot], 1u);
        unsigned gen0 = old >> 12;
        if ((old & 0xFFFu) == (unsigned)(TB_NB - 1)) {
            atomicAdd(&g_bar[slot], (1u << 12) - (unsigned)TB_NB);
        } else {
            while (((*(volatile unsigned*)&g_bar[slot]) >> 12) == gen0)
                __nanosleep(64);
        }
        __threadfence();
    }
    __syncthreads();
}
__device__ __forceinline__ void block_wait_ge(volatile int* flag, int val) {
    if (threadIdx.x == 0) {
        while (*flag < val) __nanosleep(64);
    }
    __syncthreads();
    __threadfence();
}

// ================= K1: fused — thr/base2cls/base3 producers + flag stream ====
// blocks 0..15  : thr/l1 (publish g_thr_ready), then base3 row
// block  16     : base2cls (publish g_b2_ready), then base3 row
// blocks 17..37 : base3 row (spin on g_b2_ready)
// blocks 38..1037: flag stream over x (prefetch x, spin on g_thr_ready)
__global__ __launch_bounds__(256, 5) void k_fused(
    const float4* __restrict__ x4,
    const float*  __restrict__ phi, const float* __restrict__ jumpp, int D,
    const float*  __restrict__ w2,  const float* __restrict__ b1,
    const float*  __restrict__ b2,  const float* __restrict__ w3,
    const float*  __restrict__ b3)
{
    __shared__ float s_buf[5200];   // 20.8 KB, unioned across phases
    int tid = threadIdx.x, bid = blockIdx.x;

    if (bid >= 38) {
        // ---------------- flag stream ----------------
        const float* xs = (const float*)x4;
        (void)xs;
        int ft = (bid - 38) * NT + tid;           // 0..255999
        // prefetch first batch BEFORE waiting for thr
        float4 v[8];
        #pragma unroll
        for (int k = 0; k < 8; k++) v[k] = x4[ft + k*NFT];
        block_wait_ge(&g_thr_ready, 16);
        for (int i = tid; i < CIN; i += NT) s_buf[i] = __ldcg(&g_thr[i]);
        __syncthreads();
        #pragma unroll
        for (int half = 0; half < 2; half++) {
            if (half == 1) {
                #pragma unroll
                for (int k = 0; k < 8; k++) v[k] = x4[ft + (8 + k)*NFT];
            }
            #pragma unroll
            for (int k = 0; k < 8; k++) {
                int i = ft + (half*8 + k)*NFT;
                int ehw = i >> 6;
                int c = ehw % CIN;
                float th = s_buf[c];
                if (fabsf(v[k].x) >= th || fabsf(v[k].y) >= th ||
                    fabsf(v[k].z) >= th || fabsf(v[k].w) >= th) {
                    int b = ehw / CIN;
                    int pix = b*(HIN*WIN) + ((i*4) & (HIN*WIN-1));
                    if (atomicExch(&g_flagd[pix], 1) == 0) {
                        int t0 = atomicAdd(&g_ncand, 1);
                        g_cand[t0] = pix;
                    }
                }
            }
        }
        return;
    }

    // ---------------- producers (bid < 38) ----------------
    if (bid < 16) {
        // thr/l1 for channels bid*32 .. bid*32+31
        int lane = tid & 31, w = tid >> 5;        // 8 warps
        int c = bid*32 + lane;
        float s = 0.f;
        if (c < CIN) {
            if (D == 192) {
                int d0 = w * 24;
                #pragma unroll
                for (int k = 0; k < 24; k++)
                    s += fabsf(__ldg(&phi[(d0 + k)*CIN + c]));
            } else {
                int chunk = (D + 7) >> 3;
                int d0 = w*chunk, d1e = min(D, d0 + chunk);
                for (int d = d0; d < d1e; d++) s += fabsf(phi[d*CIN + c]);
            }
        }
        s_buf[w*32 + lane] = s;
        __syncthreads();
        if (tid < 32 && bid*32 + tid < CIN) {
            float t = 1e-12f;
            #pragma unroll
            for (int k = 0; k < 8; k++) t += s_buf[k*32 + tid];
            __stcg(&g_l1[bid*32 + tid],  t);
            __stcg(&g_thr[bid*32 + tid], (*jumpp) * t);
            __threadfence();
        }
        __syncthreads();
        if (tid == 0) atomicAdd(&g_thr_ready, 1);
    } else if (bid == 16) {
        // base2cls: W[900] = sum_ci relu(b1[ci]) * w2[ci*900 + o]
        for (int i = tid; i < C1; i += NT) s_buf[3000 + i] = fmaxf(__ldg(&b1[i]), 0.f);
        __syncthreads();
        if (tid < 225) {
            float4 acc = {0.f,0.f,0.f,0.f};
            #pragma unroll 6
            for (int ci = 0; ci < C1; ci++) {
                float y = s_buf[3000 + ci];
                float4 wv = ((const float4*)(w2 + (size_t)ci*900))[tid];
                acc.x += y*wv.x; acc.y += y*wv.y; acc.z += y*wv.z; acc.w += y*wv.w;
            }
            s_buf[tid*4+0] = acc.x; s_buf[tid*4+1] = acc.y;
            s_buf[tid*4+2] = acc.z; s_buf[tid*4+3] = acc.w;
        }
        __syncthreads();
        {
            const int kmin[5] = {0,0,0,1,2}, kmax[5] = {0,1,2,2,2};
            for (int p = tid; p < 25*C2; p += NT) {
                int cls = p / C2, co = p % C2;
                int ch = cls / 5, cw = cls % 5;
                float acc = __ldg(&b2[co]);
                for (int kh = kmin[ch]; kh <= kmax[ch]; kh++)
                    for (int kw = kmin[cw]; kw <= kmax[cw]; kw++)
                        acc += s_buf[co*9 + kh*3 + kw];
                __stcg(&g_base2cls[cls*C2 + co], acc);
            }
        }
        __threadfence();
        __syncthreads();
        if (tid == 0) atomicAdd(&g_b2_ready, 1);
    }

    // ---------------- base3 row oh = bid (all blocks 0..37) ----------------
    {
        float* s_b2r = s_buf;             // 2500
        float* s_w3  = s_buf + 2500;      // 2700
        __syncthreads();                  // producers done with s_buf
        for (int i = tid; i < C2*C3*9; i += NT) s_w3[i] = w3[i];
        block_wait_ge(&g_b2_ready, 1);
        for (int i = tid; i < 25*C2; i += NT) s_b2r[i] = fmaxf(__ldcg(&g_base2cls[i]), 0.f);
        __syncthreads();
        int oh = bid;
        if (tid < C3*O3) {
            int co = tid / O3, ow = tid % O3;
            float mh[3], mw[3]; int bh[3], bw[3];
            #pragma unroll
            for (int kh = 0; kh < 3; kh++) {
                int q = oh - kh; bool v = (q >= 0 && q <= 35);
                mh[kh] = v ? 1.f : 0.f; bh[kh] = v ? cls36(q)*5 : 0;
            }
            #pragma unroll
            for (int kw = 0; kw < 3; kw++) {
                int r = ow - kw; bool v = (r >= 0 && r <= 35);
                mw[kw] = v ? 1.f : 0.f; bw[kw] = v ? cls36(r) : 0;
            }
            float m[9]; int bi[9];
            #pragma unroll
            for (int kh = 0; kh < 3; kh++)
                #pragma unroll
                for (int kw = 0; kw < 3; kw++) {
                    m[kh*3+kw]  = mh[kh]*mw[kw];
                    bi[kh*3+kw] = (bh[kh]+bw[kw])*C2;
                }
            float acc = __ldg(&b3[co]);
            for (int ci = 0; ci < C2; ci++) {
                #pragma unroll
                for (int k = 0; k < 9; k++)
                    acc += m[k] * s_b2r[bi[k] + ci] * s_w3[(ci*3 + co)*9 + k];
            }
            __stcg(&g_base3[(co*O3 + oh)*O3 + ow], acc);
        }
    }
}

// ================= K2: tail — topk | conv1 | conv2 | out | cleanup ==========
__global__ __launch_bounds__(TB_NT, 1) void k_tail(
    const float* __restrict__ x,
    const float* __restrict__ jumpp,
    const float* __restrict__ w1,
    const float* __restrict__ b1,
    const float* __restrict__ w2,
    const float* __restrict__ w3,
    float* __restrict__ out)
{
    const int tid  = threadIdx.x;
    const int gid  = blockIdx.x * TB_NT + tid;
    const int lane = tid & 31;
    const int wgid = gid >> 5;

    // ---- P0: top-30 + saturation on candidates; scatter dirty1 ----
    {
        const unsigned FULL = 0xffffffffu;
        int n = __ldcg(&g_ncand);
        if (n > 0) {
            float jump = *jumpp;
            for (int t = wgid; t < n; t += NWARPS) {
                int p = g_cand[t];
                int b = p >> 8, hw = p & 255;
                float v[16]; unsigned u[16];
                #pragma unroll
                for (int j = 0; j < 16; j++) {
                    int c = lane + 32*j;
                    float xv = (c < CIN) ? x[((size_t)b*CIN + c)*(HIN*WIN) + hw] : 0.f;
                    v[j] = xv;
                    u[j] = (c < CIN) ? __float_as_uint(fabsf(xv)) : 0u;
                }
                unsigned T = 0;
                for (int bit = 31; bit >= 0; bit--) {
                    unsigned cand = T | (1u << bit);
                    int cl = 0;
                    #pragma unroll
                    for (int j = 0; j < 16; j++) cl += (u[j] >= cand);
                    if (warp_sum(cl) >= KTOP) T = cand;
                }
                int mg = 0;
                #pragma unroll
                for (int j = 0; j < 16; j++) mg += (u[j] > T);
                int need = KTOP - warp_sum(mg);
                int cnt_out = 0, base_tie = 0;
                unsigned lmask = (1u << lane) - 1u;
                #pragma unroll
                for (int j = 0; j < 16; j++) {
                    int c = lane + 32*j;
                    bool inr = (c < CIN);
                    bool gt  = inr && (u[j] > T);
                    bool eq  = inr && (u[j] == T);
                    unsigned beq = __ballot_sync(FULL, eq);
                    int tpre = base_tie + __popc(beq & lmask);
                    base_tie += __popc(beq);
                    bool keep = gt || (eq && tpre < need);
                    float s = 0.f;
                    if (keep) {
                        float r = v[j] / __ldcg(&g_l1[c]);
                        s = 0.5f * (sgnf(r - jump) + sgnf(r + jump));
                    }
                    bool emit = keep && (s != 0.f);
                    unsigned be = __ballot_sync(FULL, emit);
                    int pos = cnt_out + __popc(be & lmask);
                    if (emit) {
                        __stcg(&g_chid[p*KTOP + pos], c);
                        __stcg(&g_qval[p*KTOP + pos], s * __ldcg(&g_l1[c]));
                    }
                    cnt_out += __popc(be);
                }
                if (cnt_out > 0) {
                    if (lane == 0) __stcg(&g_cnt[p], cnt_out);
                    int ih = (p >> 4) & 15, iw = p & 15;
                    if (lane < 16) {
                        int kh = lane >> 2, kw = lane & 3;
                        int idx = (b*O1 + 2*ih + kh)*O1 + (2*iw + kw);
                        if (atomicExch(&g_dirty1[idx], 1) == 0) {
                            int t1 = atomicAdd(&g_n1, 1);
                            __stcg(&g_list1[t1], idx);
                        }
                    }
                }
            }
        }
    }
    grid_bar(0);

    // ---- P1: conv1 delta at dirty1; scatter dirty2 ----
    {
        int n1 = __ldcg(&g_n1);
        for (int t = wgid; t < n1; t += NWARPS) {
            int idx = __ldcg(&g_list1[t]);
            int b = idx / (O1*O1), rem = idx % (O1*O1);
            int oh = rem / O1, ow = rem % O1;
            float acc[10];
            #pragma unroll
            for (int k = 0; k < 10; k++) acc[k] = 0.f;
            for (int kh = (oh & 1); kh < 4; kh += 2) {
                int dh = oh - kh; if (dh < 0 || dh > 30) continue;
                int ih = dh >> 1;
                for (int kw = (ow & 1); kw < 4; kw += 2) {
                    int dw = ow - kw; if (dw < 0 || dw > 30) continue;
                    int iw = dw >> 1;
                    int p = (b*16 + ih)*16 + iw;
                    int nz = __ldcg(&g_cnt[p]);
                    for (int e = 0; e < nz; e++) {
                        int c = __ldcg(&g_chid[p*KTOP + e]);
                        float qv = __ldcg(&g_qval[p*KTOP + e]);
                        const float* wp = w1 + (size_t)c*(C1*16) + kh*4 + kw;
                        #pragma unroll
                        for (int k = 0; k < 10; k++) {
                            int co = lane + 32*k;
                            if (co < C1) acc[k] += qv * wp[co*16];
                        }
                    }
                }
            }
            #pragma unroll
            for (int k = 0; k < 10; k++) {
                int co = lane + 32*k;
                if (co < C1) {
                    float bb = b1[co];
                    float d = fmaxf(bb + acc[k], 0.f) - fmaxf(bb, 0.f);
                    __stcg(&g_delta1[(((size_t)b*C1 + co)*O1 + oh)*O1 + ow], d);
                }
            }
            if (lane < 9) {
                int kh = lane / 3, kw = lane % 3;
                int idx2 = (b*O2 + oh + kh)*O2 + (ow + kw);
                if (atomicExch(&g_dirty2[idx2], 1) == 0) {
                    int t2 = atomicAdd(&g_n2, 1);
                    __stcg(&g_list2[t2], idx2);
                }
            }
        }
    }
    grid_bar(1);

    // ---- P2: conv2 delta at dirty2; scatter dirty3 ----
    {
        int n2 = __ldcg(&g_n2);
        for (int t = wgid; t < n2; t += NWARPS) {
            int idx = __ldcg(&g_list2[t]);
            int b = idx / (O2*O2), rem = idx % (O2*O2);
            int oh = rem / O2, ow = rem % O2;
            float acc[4] = {0.f,0.f,0.f,0.f};
            for (int kh = 0; kh < 3; kh++) {
                int q = oh - kh; if (q < 0 || q > 33) continue;
                for (int kw = 0; kw < 3; kw++) {
                    int r = ow - kw; if (r < 0 || r > 33) continue;
                    if (!__ldcg(&g_dirty1[(b*O1 + q)*O1 + r])) continue;
                    const float* dp = g_delta1 + (size_t)b*C1*O1*O1 + q*O1 + r;
                    const float* wb = w2 + kh*3 + kw;
                    for (int ci = 0; ci < C1; ci++) {
                        float dv = __ldcg(&dp[(size_t)ci*O1*O1]);
                        const float* wp = wb + (size_t)ci*(C2*9);
                        #pragma unroll
                        for (int k = 0; k < 4; k++) {
                            int co = lane + 32*k;
                            if (co < C2) acc[k] += dv * wp[co*9];
                        }
                    }
                }
            }
            int clh = cls36(oh), clw = cls36(ow);
            #pragma unroll
            for (int k = 0; k < 4; k++) {
                int co = lane + 32*k;
                if (co < C2) {
                    float pre = __ldcg(&g_base2cls[(clh*5 + clw)*C2 + co]);
                    float d = fmaxf(pre + acc[k], 0.f) - fmaxf(pre, 0.f);
                    __stcg(&g_delta2[(((size_t)b*C2 + co)*O2 + oh)*O2 + ow], d);
                }
            }
            if (lane < 9) {
                int kh = lane / 3, kw = lane % 3;
                __stcg(&g_dirty3[(b*O3 + oh + kh)*O3 + (ow + kw)], 1);
            }
        }
    }
    grid_bar(2);

    // ---- P3: output = crop(relu(base3 + conv3(delta2))) ----
    {
        const int TOT4 = BATCH*C3*32*32/4;     // 98304 float4
        #pragma unroll
        for (int t = 0; t < 2; t++) {
            int i4 = gid + t*NTHREADS;
            if (i4 >= TOT4) break;
            int xg4 = i4 & 7;
            int yg  = (i4 >> 3) & 31;
            int co  = (i4 >> 8) % 3;
            int b   = i4 / 768;
            int oh  = yg + 3;
            int ow0 = xg4*4 + 3;
            float r[4]; int dirty = 0;
            #pragma unroll
            for (int j = 0; j < 4; j++) {
                r[j] = __ldcg(&g_base3[(co*O3 + oh)*O3 + ow0 + j]);
                dirty |= __ldcg(&g_dirty3[(b*O3 + oh)*O3 + ow0 + j]);
            }
            if (dirty) {
                #pragma unroll
                for (int j = 0; j < 4; j++) {
                    int ow = ow0 + j;
                    if (!__ldcg(&g_dirty3[(b*O3 + oh)*O3 + ow])) continue;
                    for (int kh = 0; kh < 3; kh++) {
                        int q = oh - kh;
                        for (int kw = 0; kw < 3; kw++) {
                            int rr = ow - kw;
                            if (!__ldcg(&g_dirty2[(b*O2 + q)*O2 + rr])) continue;
                            for (int ci = 0; ci < C2; ci++)
                                r[j] += __ldcg(&g_delta2[(((size_t)b*C2 + ci)*O2 + q)*O2 + rr])
                                        * __ldg(&w3[((ci*3 + co)*3 + kh)*3 + kw]);
                        }
                    }
                }
            }
            float4 o4 = {fmaxf(r[0],0.f), fmaxf(r[1],0.f), fmaxf(r[2],0.f), fmaxf(r[3],0.f)};
            ((float4*)out)[i4] = o4;
        }
    }
    grid_bar(3);

    // ---- P4: self-clean scratch so next call starts from all-zero ----
    {
        int n = __ldcg(&g_ncand);
        for (int t = gid; t < n; t += NTHREADS) {
            int p = __ldcg(&g_cand[t]);
            __stcg(&g_flagd[p], 0);
            __stcg(&g_cnt[p], 0);
        }
        int n1 = __ldcg(&g_n1);
        for (int t = gid; t < n1; t += NTHREADS)
            __stcg(&g_dirty1[__ldcg(&g_list1[t])], 0);
        int n2 = __ldcg(&g_n2);
        for (int t = gid; t < n2; t += NTHREADS) {
            int idx = __ldcg(&g_list2[t]);
            int b = idx / (O2*O2), rem = idx % (O2*O2);
            int oh = rem / O2, ow = rem % O2;
            __stcg(&g_dirty2[idx], 0);
            for (int kh = 0; kh < 3; kh++)
                for (int kw = 0; kw < 3; kw++)
                    __stcg(&g_dirty3[(b*O3 + oh + kh)*O3 + (ow + kw)], 0);
        }
        if (gid == 0) {
            __stcg(&g_ncand, 0); __stcg(&g_n1, 0); __stcg(&g_n2, 0);
            __stcg(&g_thr_ready, 0); __stcg(&g_b2_ready, 0);
        }
    }
}

// ---------------- launch ----------------
extern "C" void kernel_launch(void* const* d_in, const int* in_sizes, int n_in,
                              void* d_out, int out_size) {
    const float* x    = (const float*)d_in[0];
    const float* phi  = (const float*)d_in[1];
    const float* jump = (const float*)d_in[2];
    const float* w1   = (const float*)d_in[3];
    const float* b1   = (const float*)d_in[4];
    const float* w2   = (const float*)d_in[5];
    const float* b2   = (const float*)d_in[6];
    const float* w3   = (const float*)d_in[7];
    const float* b3   = (const float*)d_in[8];
    float* out = (float*)d_out;
    int D = in_sizes[1] / CIN;   // 192

    k_fused<<<1038, NT>>>((const float4*)x, phi, jump, D, w2, b1, b2, w3, b3);
    k_tail<<<TB_NB, TB_NT>>>(x, jump, w1, b1, w2, w3, out);
    (void)n_in; (void)out_size;
}

// round 10
// speedup vs baseline: 1.0901x; 1.0901x over previous
#include <cuda_runtime.h>

// ---------------- problem constants ----------------
#define BATCH 128
#define CIN   500
#define HIN   16
#define WIN   16
#define NPIX  (BATCH*HIN*WIN)     // 32768
#define KTOP  30

#define C1 300
#define O1 34
#define C2 100
#define O2 36
#define C3 3
#define O3 38

// k_tail: 296 blocks x 256 threads (148 SMs x 2, co-resident) — R8-proven shape
#define NB 296
#define NT 256
#define NTHREADS (NB*NT)          // 75776
#define NWARPS (NTHREADS/32)      // 2368

#define NFT 256000                // flag threads: 1000 blocks x 256
#define N4 (BATCH*CIN*HIN*WIN/4)  // 4,096,000 float4 = 16 * NFT exactly

// ---------------- static device scratch (zero at module load; self-cleaned) --
__device__ float g_l1[CIN];
__device__ float g_thr[CIN];
__device__ int   g_flagd[NPIX];
__device__ int   g_cand[NPIX];
__device__ int   g_ncand;
__device__ int   g_cnt[NPIX];
__device__ int   g_chid[NPIX*KTOP];
__device__ float g_qval[NPIX*KTOP];

__device__ int   g_dirty1[BATCH*O1*O1];
__device__ int   g_dirty2[BATCH*O2*O2];
__device__ int   g_dirty3[BATCH*O3*O3];
__device__ int   g_list1[BATCH*O1*O1];
__device__ int   g_list2[BATCH*O2*O2];
__device__ int   g_n1, g_n2;

__device__ float g_delta1[BATCH*C1*O1*O1];
__device__ float g_delta2[BATCH*C2*O2*O2];

__device__ float g_base2cls[25*C2];
__device__ float g_base3[C3*O3*O3];

__device__ int g_ready;           // 16 (thr blocks) + 16 (cleanup block) = 32
__device__ int g_b2_ready;
__device__ unsigned g_bar[4];     // packed count[0:12)/gen[12:32), monotonic

// ---------------- helpers ----------------
__device__ __forceinline__ float sgnf(float a) {
    return (float)((a > 0.f) - (a < 0.f));
}
__device__ __forceinline__ int warp_sum(int v) {
    #pragma unroll
    for (int o = 16; o > 0; o >>= 1) v += __shfl_xor_sync(0xffffffffu, v, o);
    return v;
}
__device__ __forceinline__ int cls36(int q) {
    return (q == 0) ? 0 : (q == 1) ? 1 : (q <= 33) ? 2 : (q == 34) ? 3 : 4;
}
__device__ __forceinline__ void grid_bar(int slot) {
    __syncthreads();
    if (threadIdx.x == 0) {
        __threadfence();
        unsigned old = atomicAdd(&g_bar[slot], 1u);
        unsigned gen0 = old >> 12;
        if ((old & 0xFFFu) == (unsigned)(NB - 1)) {
            atomicAdd(&g_bar[slot], (1u << 12) - (unsigned)NB);
        } else {
            while (((*(volatile unsigned*)&g_bar[slot]) >> 12) == gen0)
                __nanosleep(64);
        }
        __threadfence();
    }
    __syncthreads();
}
__device__ __forceinline__ void block_wait_ge(volatile int* flag, int val) {
    if (threadIdx.x == 0) {
        while (*flag < val) __nanosleep(64);
    }
    __syncthreads();
    __threadfence();
}

// ================= K1: fused — cleanup/thr/base2cls/base3 + flag stream =====
// blocks 0..15  : thr/l1 (add 1 to g_ready each), then base3 row
// block  16     : base2cls (publish g_b2_ready), then base3 row
// block  17     : cleanup prev-call scratch + reset counters (add 16), base3 row
// blocks 18..37 : base3 row (spin on g_b2_ready)
// blocks 38..1037: flag stream over x (prefetch x, spin on g_ready==32)
__global__ __launch_bounds__(256, 5) void k_fused(
    const float4* __restrict__ x4,
    const float*  __restrict__ phi, const float* __restrict__ jumpp, int D,
    const float*  __restrict__ w2,  const float* __restrict__ b1,
    const float*  __restrict__ b2,  const float* __restrict__ w3,
    const float*  __restrict__ b3)
{
    __shared__ float s_buf[5200];   // 20.8 KB, unioned across phases
    int tid = threadIdx.x, bid = blockIdx.x;

    if (bid >= 38) {
        // ---------------- flag stream ----------------
        int ft = (bid - 38) * NT + tid;           // 0..255999
        // prefetch first batch BEFORE waiting for ready
        float4 v[8];
        #pragma unroll
        for (int k = 0; k < 8; k++) v[k] = x4[ft + k*NFT];
        block_wait_ge(&g_ready, 32);
        for (int i = tid; i < CIN; i += NT) s_buf[i] = __ldcg(&g_thr[i]);
        __syncthreads();
        #pragma unroll
        for (int half = 0; half < 2; half++) {
            if (half == 1) {
                #pragma unroll
                for (int k = 0; k < 8; k++) v[k] = x4[ft + (8 + k)*NFT];
            }
            #pragma unroll
            for (int k = 0; k < 8; k++) {
                int i = ft + (half*8 + k)*NFT;
                int ehw = i >> 6;
                int c = ehw % CIN;
                float th = s_buf[c];
                if (fabsf(v[k].x) >= th || fabsf(v[k].y) >= th ||
                    fabsf(v[k].z) >= th || fabsf(v[k].w) >= th) {
                    int b = ehw / CIN;
                    int pix = b*(HIN*WIN) + ((i*4) & (HIN*WIN-1));
                    if (atomicExch(&g_flagd[pix], 1) == 0) {
                        int t0 = atomicAdd(&g_ncand, 1);
                        g_cand[t0] = pix;
                    }
                }
            }
        }
        return;
    }

    // ---------------- producers (bid < 38) ----------------
    if (bid < 16) {
        // thr/l1 for channels bid*32 .. bid*32+31
        int lane = tid & 31, w = tid >> 5;        // 8 warps
        int c = bid*32 + lane;
        float s = 0.f;
        if (c < CIN) {
            if (D == 192) {
                int d0 = w * 24;
                #pragma unroll
                for (int k = 0; k < 24; k++)
                    s += fabsf(__ldg(&phi[(d0 + k)*CIN + c]));
            } else {
                int chunk = (D + 7) >> 3;
                int d0 = w*chunk, d1e = min(D, d0 + chunk);
                for (int d = d0; d < d1e; d++) s += fabsf(phi[d*CIN + c]);
            }
        }
        s_buf[w*32 + lane] = s;
        __syncthreads();
        if (tid < 32 && bid*32 + tid < CIN) {
            float t = 1e-12f;
            #pragma unroll
            for (int k = 0; k < 8; k++) t += s_buf[k*32 + tid];
            __stcg(&g_l1[bid*32 + tid],  t);
            __stcg(&g_thr[bid*32 + tid], (*jumpp) * t);
            __threadfence();
        }
        __syncthreads();
        if (tid == 0) atomicAdd(&g_ready, 1);
    } else if (bid == 16) {
        // base2cls: W[900] = sum_ci relu(b1[ci]) * w2[ci*900 + o]
        for (int i = tid; i < C1; i += NT) s_buf[3000 + i] = fmaxf(__ldg(&b1[i]), 0.f);
        __syncthreads();
        if (tid < 225) {
            float4 acc = {0.f,0.f,0.f,0.f};
            #pragma unroll 6
            for (int ci = 0; ci < C1; ci++) {
                float y = s_buf[3000 + ci];
                float4 wv = ((const float4*)(w2 + (size_t)ci*900))[tid];
                acc.x += y*wv.x; acc.y += y*wv.y; acc.z += y*wv.z; acc.w += y*wv.w;
            }
            s_buf[tid*4+0] = acc.x; s_buf[tid*4+1] = acc.y;
            s_buf[tid*4+2] = acc.z; s_buf[tid*4+3] = acc.w;
        }
        __syncthreads();
        {
            const int kmin[5] = {0,0,0,1,2}, kmax[5] = {0,1,2,2,2};
            for (int p = tid; p < 25*C2; p += NT) {
                int cls = p / C2, co = p % C2;
                int ch = cls / 5, cw = cls % 5;
                float acc = __ldg(&b2[co]);
                for (int kh = kmin[ch]; kh <= kmax[ch]; kh++)
                    for (int kw = kmin[cw]; kw <= kmax[cw]; kw++)
                        acc += s_buf[co*9 + kh*3 + kw];
                __stcg(&g_base2cls[cls*C2 + co], acc);
            }
        }
        __threadfence();
        __syncthreads();
        if (tid == 0) atomicAdd(&g_b2_ready, 1);
    } else if (bid == 17) {
        // cleanup of prev call's scratch (lists persisted; empty in practice)
        int n = g_ncand;
        for (int t = tid; t < n; t += NT) {
            int p = g_cand[t];
            __stcg(&g_flagd[p], 0);
            __stcg(&g_cnt[p], 0);
        }
        int n1 = g_n1;
        for (int t = tid; t < n1; t += NT)
            __stcg(&g_dirty1[g_list1[t]], 0);
        int n2 = g_n2;
        for (int t = tid; t < n2; t += NT) {
            int idx = g_list2[t];
            int b = idx / (O2*O2), rem = idx % (O2*O2);
            int oh = rem / O2, ow = rem % O2;
            __stcg(&g_dirty2[idx], 0);
            for (int kh = 0; kh < 3; kh++)
                for (int kw = 0; kw < 3; kw++)
                    __stcg(&g_dirty3[(b*O3 + oh + kh)*O3 + (ow + kw)], 0);
        }
        __syncthreads();
        if (tid == 0) {
            __stcg(&g_ncand, 0); __stcg(&g_n1, 0); __stcg(&g_n2, 0);
            __threadfence();
            atomicAdd(&g_ready, 16);
        }
        __syncthreads();
    }

    // ---------------- base3 row oh = bid (all blocks 0..37) ----------------
    {
        float* s_b2r = s_buf;             // 2500
        float* s_w3  = s_buf + 2500;      // 2700
        __syncthreads();                  // producers done with s_buf
        for (int i = tid; i < C2*C3*9; i += NT) s_w3[i] = w3[i];
        block_wait_ge(&g_b2_ready, 1);
        for (int i = tid; i < 25*C2; i += NT) s_b2r[i] = fmaxf(__ldcg(&g_base2cls[i]), 0.f);
        __syncthreads();
        int oh = bid;
        if (tid < C3*O3) {
            int co = tid / O3, ow = tid % O3;
            float mh[3], mw[3]; int bh[3], bw[3];
            #pragma unroll
            for (int kh = 0; kh < 3; kh++) {
                int q = oh - kh; bool v = (q >= 0 && q <= 35);
                mh[kh] = v ? 1.f : 0.f; bh[kh] = v ? cls36(q)*5 : 0;
            }
            #pragma unroll
            for (int kw = 0; kw < 3; kw++) {
                int r = ow - kw; bool v = (r >= 0 && r <= 35);
                mw[kw] = v ? 1.f : 0.f; bw[kw] = v ? cls36(r) : 0;
            }
            float m[9]; int bi[9];
            #pragma unroll
            for (int kh = 0; kh < 3; kh++)
                #pragma unroll
                for (int kw = 0; kw < 3; kw++) {
                    m[kh*3+kw]  = mh[kh]*mw[kw];
                    bi[kh*3+kw] = (bh[kh]+bw[kw])*C2;
                }
            float acc = __ldg(&b3[co]);
            for (int ci = 0; ci < C2; ci++) {
                #pragma unroll
                for (int k = 0; k < 9; k++)
                    acc += m[k] * s_b2r[bi[k] + ci] * s_w3[(ci*3 + co)*9 + k];
            }
            __stcg(&g_base3[(co*O3 + oh)*O3 + ow], acc);
        }
    }
}

// ================= K2: tail — topk | conv1 | conv2 | out (R8 shape) =========
__global__ __launch_bounds__(NT, 2) void k_tail(
    const float* __restrict__ x,
    const float* __restrict__ jumpp,
    const float* __restrict__ w1,
    const float* __restrict__ b1,
    const float* __restrict__ w2,
    const float* __restrict__ w3,
    float* __restrict__ out)
{
    const int tid  = threadIdx.x;
    const int gid  = blockIdx.x * NT + tid;
    const int lane = tid & 31;
    const int wgid = gid >> 5;

    if (gid == 0) { g_ready = 0; g_b2_ready = 0; }   // safe: kernel ordering

    // ---- P0: top-30 + saturation on candidates; scatter dirty1 ----
    {
        const unsigned FULL = 0xffffffffu;
        int n = g_ncand;
        if (n > 0) {
            float jump = *jumpp;
            for (int t = wgid; t < n; t += NWARPS) {
                int p = g_cand[t];
                int b = p >> 8, hw = p & 255;
                float v[16]; unsigned u[16];
                #pragma unroll
                for (int j = 0; j < 16; j++) {
                    int c = lane + 32*j;
                    float xv = (c < CIN) ? x[((size_t)b*CIN + c)*(HIN*WIN) + hw] : 0.f;
                    v[j] = xv;
                    u[j] = (c < CIN) ? __float_as_uint(fabsf(xv)) : 0u;
                }
                unsigned T = 0;
                for (int bit = 31; bit >= 0; bit--) {
                    unsigned cand = T | (1u << bit);
                    int cl = 0;
                    #pragma unroll
                    for (int j = 0; j < 16; j++) cl += (u[j] >= cand);
                    if (warp_sum(cl) >= KTOP) T = cand;
                }
                int mg = 0;
                #pragma unroll
                for (int j = 0; j < 16; j++) mg += (u[j] > T);
                int need = KTOP - warp_sum(mg);
                int cnt_out = 0, base_tie = 0;
                unsigned lmask = (1u << lane) - 1u;
                #pragma unroll
                for (int j = 0; j < 16; j++) {
                    int c = lane + 32*j;
                    bool inr = (c < CIN);
                    bool gt  = inr && (u[j] > T);
                    bool eq  = inr && (u[j] == T);
                    unsigned beq = __ballot_sync(FULL, eq);
                    int tpre = base_tie + __popc(beq & lmask);
                    base_tie += __popc(beq);
                    bool keep = gt || (eq && tpre < need);
                    float s = 0.f;
                    if (keep) {
                        float r = v[j] / g_l1[c];
                        s = 0.5f * (sgnf(r - jump) + sgnf(r + jump));
                    }
                    bool emit = keep && (s != 0.f);
                    unsigned be = __ballot_sync(FULL, emit);
                    int pos = cnt_out + __popc(be & lmask);
                    if (emit) {
                        __stcg(&g_chid[p*KTOP + pos], c);
                        __stcg(&g_qval[p*KTOP + pos], s * g_l1[c]);
                    }
                    cnt_out += __popc(be);
                }
                if (cnt_out > 0) {
                    if (lane == 0) __stcg(&g_cnt[p], cnt_out);
                    int ih = (p >> 4) & 15, iw = p & 15;
                    if (lane < 16) {
                        int kh = lane >> 2, kw = lane & 3;
                        int idx = (b*O1 + 2*ih + kh)*O1 + (2*iw + kw);
                        if (atomicExch(&g_dirty1[idx], 1) == 0) {
                            int t1 = atomicAdd(&g_n1, 1);
                            __stcg(&g_list1[t1], idx);
                        }
                    }
                }
            }
        }
    }
    grid_bar(0);

    // ---- P1: conv1 delta at dirty1; scatter dirty2 ----
    {
        int n1 = __ldcg(&g_n1);
        for (int t = wgid; t < n1; t += NWARPS) {
            int idx = __ldcg(&g_list1[t]);
            int b = idx / (O1*O1), rem = idx % (O1*O1);
            int oh = rem / O1, ow = rem % O1;
            float acc[10];
            #pragma unroll
            for (int k = 0; k < 10; k++) acc[k] = 0.f;
            for (int kh = (oh & 1); kh < 4; kh += 2) {
                int dh = oh - kh; if (dh < 0 || dh > 30) continue;
                int ih = dh >> 1;
                for (int kw = (ow & 1); kw < 4; kw += 2) {
                    int dw = ow - kw; if (dw < 0 || dw > 30) continue;
                    int iw = dw >> 1;
                    int p = (b*16 + ih)*16 + iw;
                    int nz = __ldcg(&g_cnt[p]);
                    for (int e = 0; e < nz; e++) {
                        int c = __ldcg(&g_chid[p*KTOP + e]);
                        float qv = __ldcg(&g_qval[p*KTOP + e]);
                        const float* wp = w1 + (size_t)c*(C1*16) + kh*4 + kw;
                        #pragma unroll
                        for (int k = 0; k < 10; k++) {
                            int co = lane + 32*k;
                            if (co < C1) acc[k] += qv * wp[co*16];
                        }
                    }
                }
            }
            #pragma unroll
            for (int k = 0; k < 10; k++) {
                int co = lane + 32*k;
                if (co < C1) {
                    float bb = b1[co];
                    float d = fmaxf(bb + acc[k], 0.f) - fmaxf(bb, 0.f);
                    __stcg(&g_delta1[(((size_t)b*C1 + co)*O1 + oh)*O1 + ow], d);
                }
            }
            if (lane < 9) {
                int kh = lane / 3, kw = lane % 3;
                int idx2 = (b*O2 + oh + kh)*O2 + (ow + kw);
                if (atomicExch(&g_dirty2[idx2], 1) == 0) {
                    int t2 = atomicAdd(&g_n2, 1);
                    __stcg(&g_list2[t2], idx2);
                }
            }
        }
    }
    grid_bar(1);

    // ---- P2: conv2 delta at dirty2; scatter dirty3 ----
    {
        int n2 = __ldcg(&g_n2);
        for (int t = wgid; t < n2; t += NWARPS) {
            int idx = __ldcg(&g_list2[t]);
            int b = idx / (O2*O2), rem = idx % (O2*O2);
            int oh = rem / O2, ow = rem % O2;
            float acc[4] = {0.f,0.f,0.f,0.f};
            for (int kh = 0; kh < 3; kh++) {
                int q = oh - kh; if (q < 0 || q > 33) continue;
                for (int kw = 0; kw < 3; kw++) {
                    int r = ow - kw; if (r < 0 || r > 33) continue;
                    if (!__ldcg(&g_dirty1[(b*O1 + q)*O1 + r])) continue;
                    const float* dp = g_delta1 + (size_t)b*C1*O1*O1 + q*O1 + r;
                    const float* wb = w2 + kh*3 + kw;
                    for (int ci = 0; ci < C1; ci++) {
                        float dv = __ldcg(&dp[(size_t)ci*O1*O1]);
                        const float* wp = wb + (size_t)ci*(C2*9);
                        #pragma unroll
                        for (int k = 0; k < 4; k++) {
                            int co = lane + 32*k;
                            if (co < C2) acc[k] += dv * wp[co*9];
                        }
                    }
                }
            }
            int clh = cls36(oh), clw = cls36(ow);
            #pragma unroll
            for (int k = 0; k < 4; k++) {
                int co = lane + 32*k;
                if (co < C2) {
                    float pre = g_base2cls[(clh*5 + clw)*C2 + co];
                    float d = fmaxf(pre + acc[k], 0.f) - fmaxf(pre, 0.f);
                    __stcg(&g_delta2[(((size_t)b*C2 + co)*O2 + oh)*O2 + ow], d);
                }
            }
            if (lane < 9) {
                int kh = lane / 3, kw = lane % 3;
                __stcg(&g_dirty3[(b*O3 + oh + kh)*O3 + (ow + kw)], 1);
            }
        }
    }
    grid_bar(2);

    // ---- P3: output = crop(relu(base3 + conv3(delta2))) ----
    {
        const int TOT4 = BATCH*C3*32*32/4;     // 98304 float4
        #pragma unroll
        for (int t = 0; t < 2; t++) {
            int i4 = gid + t*NTHREADS;
            if (i4 >= TOT4) break;
            int xg4 = i4 & 7;
            int yg  = (i4 >> 3) & 31;
            int co  = (i4 >> 8) % 3;
            int b   = i4 / 768;
            int oh  = yg + 3;
            int ow0 = xg4*4 + 3;
            float r[4]; int dirty = 0;
            #pragma unroll
            for (int j = 0; j < 4; j++) {
                r[j] = g_base3[(co*O3 + oh)*O3 + ow0 + j];
                dirty |= __ldcg(&g_dirty3[(b*O3 + oh)*O3 + ow0 + j]);
            }
            if (dirty) {
                #pragma unroll
                for (int j = 0; j < 4; j++) {
                    int ow = ow0 + j;
                    if (!__ldcg(&g_dirty3[(b*O3 + oh)*O3 + ow])) continue;
                    for (int kh = 0; kh < 3; kh++) {
                        int q = oh - kh;
                        for (int kw = 0; kw < 3; kw++) {
                            int rr = ow - kw;
                            if (!__ldcg(&g_dirty2[(b*O2 + q)*O2 + rr])) continue;
                            for (int ci = 0; ci < C2; ci++)
                                r[j] += __ldcg(&g_delta2[(((size_t)b*C2 + ci)*O2 + q)*O2 + rr])
                                        * __ldg(&w3[((ci*3 + co)*3 + kh)*3 + kw]);
                        }
                    }
                }
            }
            float4 o4 = {fmaxf(r[0],0.f), fmaxf(r[1],0.f), fmaxf(r[2],0.f), fmaxf(r[3],0.f)};
            ((float4*)out)[i4] = o4;
        }
    }
}

// ---------------- launch ----------------
extern "C" void kernel_launch(void* const* d_in, const int* in_sizes, int n_in,
                              void* d_out, int out_size) {
    const float* x    = (const float*)d_in[0];
    const float* phi  = (const float*)d_in[1];
    const float* jump = (const float*)d_in[2];
    const float* w1   = (const float*)d_in[3];
    const float* b1   = (const float*)d_in[4];
    const float* w2   = (const float*)d_in[5];
    const float* b2   = (const float*)d_in[6];
    const float* w3   = (const float*)d_in[7];
    const float* b3   = (const float*)d_in[8];
    float* out = (float*)d_out;
    int D = in_sizes[1] / CIN;   // 192

    k_fused<<<1038, NT>>>((const float4*)x, phi, jump, D, w2, b1, b2, w3, b3);
    k_tail<<<NB, NT>>>(x, jump, w1, b1, w2, w3, out);
    (void)n_in; (void)out_size;
}

// round 11
// speedup vs baseline: 1.2792x; 1.1735x over previous
#include <cuda_runtime.h>

// ---------------- problem constants ----------------
#define BATCH 128
#define CIN   500
#define HIN   16
#define WIN   16
#define NPIX  (BATCH*HIN*WIN)     // 32768
#define KTOP  30

#define C1 300
#define O1 34
#define C2 100
#define O2 36
#define C3 3
#define O3 38

// k_tail: 296 blocks x 256 threads (148 SMs x 2, co-resident)
#define NB 296
#define NT 256
#define NTHREADS (NB*NT)          // 75776
#define NWARPS (NTHREADS/32)      // 2368

#define NFT 256000                // flag threads: 1000 blocks x 256
#define N4 (BATCH*CIN*HIN*WIN/4)  // 4,096,000 float4 = 16 * NFT exactly

// ---------------- static device scratch (zero at module load; self-cleaned) --
__device__ float g_l1[CIN];
__device__ float g_thr[CIN];
__device__ int   g_flagd[NPIX];
__device__ int   g_cand[NPIX];
__device__ int   g_ncand;
__device__ int   g_cnt[NPIX];
__device__ int   g_chid[NPIX*KTOP];
__device__ float g_qval[NPIX*KTOP];

__device__ int   g_dirty1[BATCH*O1*O1];
__device__ int   g_dirty2[BATCH*O2*O2];
__device__ int   g_dirty3[BATCH*O3*O3];
__device__ int   g_list1[BATCH*O1*O1];
__device__ int   g_list2[BATCH*O2*O2];
__device__ int   g_n1, g_n2;

__device__ float g_delta1[BATCH*C1*O1*O1];
__device__ float g_delta2[BATCH*C2*O2*O2];

__device__ float g_base2cls[25*C2];
__device__ float g_base3[C3*O3*O3];

__device__ int g_ready;           // 16 (thr blocks) + 16 (cleanup block) = 32
__device__ int g_b2_ready;
__device__ unsigned g_bar[4];     // packed count[0:12)/gen[12:32), monotonic

// ---------------- helpers ----------------
__device__ __forceinline__ float sgnf(float a) {
    return (float)((a > 0.f) - (a < 0.f));
}
__device__ __forceinline__ int warp_sum(int v) {
    #pragma unroll
    for (int o = 16; o > 0; o >>= 1) v += __shfl_xor_sync(0xffffffffu, v, o);
    return v;
}
__device__ __forceinline__ int cls36(int q) {
    return (q == 0) ? 0 : (q == 1) ? 1 : (q <= 33) ? 2 : (q == 34) ? 3 : 4;
}
__device__ __forceinline__ void grid_bar(int slot) {
    __syncthreads();
    if (threadIdx.x == 0) {
        __threadfence();
        unsigned old = atomicAdd(&g_bar[slot], 1u);
        unsigned gen0 = old >> 12;
        if ((old & 0xFFFu) == (unsigned)(NB - 1)) {
            atomicAdd(&g_bar[slot], (1u << 12) - (unsigned)NB);
        } else {
            while (((*(volatile unsigned*)&g_bar[slot]) >> 12) == gen0)
                __nanosleep(64);
        }
        __threadfence();
    }
    __syncthreads();
}
__device__ __forceinline__ void block_wait_ge(volatile int* flag, int val) {
    if (threadIdx.x == 0) {
        while (*flag < val) __nanosleep(64);
    }
    __syncthreads();
    __threadfence();
}

// ================= K1: fused — cleanup/thr/base2cls/base3 + flag stream =====
// blocks 0..15  : thr/l1 (add 1 to g_ready each), then base3 row
// block  16     : base2cls (publish g_b2_ready), then base3 row
// block  17     : cleanup prev-call scratch + reset counters (add 16), base3 row
// blocks 18..37 : base3 row (spin on g_b2_ready)
// blocks 38..1037: flag stream over x (prefetch x, spin on g_ready==32)
__global__ __launch_bounds__(256, 5) void k_fused(
    const float4* __restrict__ x4,
    const float*  __restrict__ phi, const float* __restrict__ jumpp, int D,
    const float*  __restrict__ w2,  const float* __restrict__ b1,
    const float*  __restrict__ b2,  const float* __restrict__ w3,
    const float*  __restrict__ b3)
{
    __shared__ float s_buf[5200];   // 20.8 KB, unioned across phases
    int tid = threadIdx.x, bid = blockIdx.x;

    if (bid >= 38) {
        // ---------------- flag stream ----------------
        int ft = (bid - 38) * NT + tid;           // 0..255999
        // prefetch first batch BEFORE waiting for ready
        float4 v[8];
        #pragma unroll
        for (int k = 0; k < 8; k++) v[k] = x4[ft + k*NFT];
        block_wait_ge(&g_ready, 32);
        for (int i = tid; i < CIN; i += NT) s_buf[i] = __ldcg(&g_thr[i]);
        __syncthreads();
        #pragma unroll
        for (int half = 0; half < 2; half++) {
            if (half == 1) {
                #pragma unroll
                for (int k = 0; k < 8; k++) v[k] = x4[ft + (8 + k)*NFT];
            }
            #pragma unroll
            for (int k = 0; k < 8; k++) {
                int i = ft + (half*8 + k)*NFT;
                int ehw = i >> 6;
                int c = ehw % CIN;
                float th = s_buf[c];
                if (fabsf(v[k].x) >= th || fabsf(v[k].y) >= th ||
                    fabsf(v[k].z) >= th || fabsf(v[k].w) >= th) {
                    int b = ehw / CIN;
                    int pix = b*(HIN*WIN) + ((i*4) & (HIN*WIN-1));
                    if (atomicExch(&g_flagd[pix], 1) == 0) {
                        int t0 = atomicAdd(&g_ncand, 1);
                        g_cand[t0] = pix;
                    }
                }
            }
        }
        return;
    }

    // ---------------- producers (bid < 38) ----------------
    if (bid < 16) {
        // thr/l1 for channels bid*32 .. bid*32+31
        int lane = tid & 31, w = tid >> 5;        // 8 warps
        int c = bid*32 + lane;
        float s = 0.f;
        if (c < CIN) {
            if (D == 192) {
                int d0 = w * 24;
                #pragma unroll
                for (int k = 0; k < 24; k++)
                    s += fabsf(__ldg(&phi[(d0 + k)*CIN + c]));
            } else {
                int chunk = (D + 7) >> 3;
                int d0 = w*chunk, d1e = min(D, d0 + chunk);
                for (int d = d0; d < d1e; d++) s += fabsf(phi[d*CIN + c]);
            }
        }
        s_buf[w*32 + lane] = s;
        __syncthreads();
        if (tid < 32 && bid*32 + tid < CIN) {
            float t = 1e-12f;
            #pragma unroll
            for (int k = 0; k < 8; k++) t += s_buf[k*32 + tid];
            __stcg(&g_l1[bid*32 + tid],  t);
            __stcg(&g_thr[bid*32 + tid], (*jumpp) * t);
            __threadfence();
        }
        __syncthreads();
        if (tid == 0) atomicAdd(&g_ready, 1);
    } else if (bid == 16) {
        // base2cls: W[900] = sum_ci relu(b1[ci]) * w2[ci*900 + o]
        for (int i = tid; i < C1; i += NT) s_buf[3000 + i] = fmaxf(__ldg(&b1[i]), 0.f);
        __syncthreads();
        if (tid < 225) {
            float4 acc = {0.f,0.f,0.f,0.f};
            #pragma unroll 6
            for (int ci = 0; ci < C1; ci++) {
                float y = s_buf[3000 + ci];
                float4 wv = ((const float4*)(w2 + (size_t)ci*900))[tid];
                acc.x += y*wv.x; acc.y += y*wv.y; acc.z += y*wv.z; acc.w += y*wv.w;
            }
            s_buf[tid*4+0] = acc.x; s_buf[tid*4+1] = acc.y;
            s_buf[tid*4+2] = acc.z; s_buf[tid*4+3] = acc.w;
        }
        __syncthreads();
        {
            const int kmin[5] = {0,0,0,1,2}, kmax[5] = {0,1,2,2,2};
            for (int p = tid; p < 25*C2; p += NT) {
                int cls = p / C2, co = p % C2;
                int ch = cls / 5, cw = cls % 5;
                float acc = __ldg(&b2[co]);
                for (int kh = kmin[ch]; kh <= kmax[ch]; kh++)
                    for (int kw = kmin[cw]; kw <= kmax[cw]; kw++)
                        acc += s_buf[co*9 + kh*3 + kw];
                __stcg(&g_base2cls[cls*C2 + co], acc);
            }
        }
        __threadfence();
        __syncthreads();
        if (tid == 0) atomicAdd(&g_b2_ready, 1);
    } else if (bid == 17) {
        // cleanup of prev call's scratch (lists persisted; empty in practice)
        int n = g_ncand;
        for (int t = tid; t < n; t += NT) {
            int p = g_cand[t];
            __stcg(&g_flagd[p], 0);
            __stcg(&g_cnt[p], 0);
        }
        int n1 = g_n1;
        for (int t = tid; t < n1; t += NT)
            __stcg(&g_dirty1[g_list1[t]], 0);
        int n2 = g_n2;
        for (int t = tid; t < n2; t += NT) {
            int idx = g_list2[t];
            int b = idx / (O2*O2), rem = idx % (O2*O2);
            int oh = rem / O2, ow = rem % O2;
            __stcg(&g_dirty2[idx], 0);
            for (int kh = 0; kh < 3; kh++)
                for (int kw = 0; kw < 3; kw++)
                    __stcg(&g_dirty3[(b*O3 + oh + kh)*O3 + (ow + kw)], 0);
        }
        __syncthreads();
        if (tid == 0) {
            __stcg(&g_ncand, 0); __stcg(&g_n1, 0); __stcg(&g_n2, 0);
            __threadfence();
            atomicAdd(&g_ready, 16);
        }
        __syncthreads();
    }

    // ---------------- base3 row oh = bid (all blocks 0..37) ----------------
    {
        float* s_b2r = s_buf;             // 2500
        float* s_w3  = s_buf + 2500;      // 2700
        __syncthreads();                  // producers done with s_buf
        for (int i = tid; i < C2*C3*9; i += NT) s_w3[i] = w3[i];
        block_wait_ge(&g_b2_ready, 1);
        for (int i = tid; i < 25*C2; i += NT) s_b2r[i] = fmaxf(__ldcg(&g_base2cls[i]), 0.f);
        __syncthreads();
        int oh = bid;
        if (tid < C3*O3) {
            int co = tid / O3, ow = tid % O3;
            float mh[3], mw[3]; int bh[3], bw[3];
            #pragma unroll
            for (int kh = 0; kh < 3; kh++) {
                int q = oh - kh; bool v = (q >= 0 && q <= 35);
                mh[kh] = v ? 1.f : 0.f; bh[kh] = v ? cls36(q)*5 : 0;
            }
            #pragma unroll
            for (int kw = 0; kw < 3; kw++) {
                int r = ow - kw; bool v = (r >= 0 && r <= 35);
                mw[kw] = v ? 1.f : 0.f; bw[kw] = v ? cls36(r) : 0;
            }
            float m[9]; int bi[9];
            #pragma unroll
            for (int kh = 0; kh < 3; kh++)
                #pragma unroll
                for (int kw = 0; kw < 3; kw++) {
                    m[kh*3+kw]  = mh[kh]*mw[kw];
                    bi[kh*3+kw] = (bh[kh]+bw[kw])*C2;
                }
            float acc = __ldg(&b3[co]);
            for (int ci = 0; ci < C2; ci++) {
                #pragma unroll
                for (int k = 0; k < 9; k++)
                    acc += m[k] * s_b2r[bi[k] + ci] * s_w3[(ci*3 + co)*9 + k];
            }
            __stcg(&g_base3[(co*O3 + oh)*O3 + ow], acc);
        }
    }
}

// ================= K2: tail — fast path (ncand==0) or barriered general =====
__global__ __launch_bounds__(NT, 2) void k_tail(
    const float* __restrict__ x,
    const float* __restrict__ jumpp,
    const float* __restrict__ w1,
    const float* __restrict__ b1,
    const float* __restrict__ w2,
    const float* __restrict__ w3,
    float* __restrict__ out)
{
    const int tid  = threadIdx.x;
    const int gid  = blockIdx.x * NT + tid;
    const int lane = tid & 31;
    const int wgid = gid >> 5;

    if (gid == 0) { g_ready = 0; g_b2_ready = 0; }   // safe: kernel ordering

    // g_ncand was finalized by k_fused before this kernel launched: stable,
    // uniform across the whole grid -> uniform branch, no barrier divergence.
    const int n = __ldcg(&g_ncand);

    if (n == 0) {
        // ======== FAST PATH: quantized input is exactly zero everywhere ======
        // All delta lists empty, all dirty bits zero -> out = relu(base3 crop),
        // broadcast over batch. No grid barriers at all.
        const int TOT4 = BATCH*C3*32*32/4;     // 98304 float4
        #pragma unroll
        for (int t = 0; t < 2; t++) {
            int i4 = gid + t*NTHREADS;
            if (i4 >= TOT4) break;
            int xg4 = i4 & 7;
            int yg  = (i4 >> 3) & 31;
            int co  = (i4 >> 8) % 3;
            int oh  = yg + 3;
            int ow0 = xg4*4 + 3;
            float4 o4;
            o4.x = fmaxf(__ldcg(&g_base3[(co*O3 + oh)*O3 + ow0 + 0]), 0.f);
            o4.y = fmaxf(__ldcg(&g_base3[(co*O3 + oh)*O3 + ow0 + 1]), 0.f);
            o4.z = fmaxf(__ldcg(&g_base3[(co*O3 + oh)*O3 + ow0 + 2]), 0.f);
            o4.w = fmaxf(__ldcg(&g_base3[(co*O3 + oh)*O3 + ow0 + 3]), 0.f);
            ((float4*)out)[i4] = o4;
        }
        return;
    }

    // ======== GENERAL PATH (n > 0): full sparse-delta pipeline ===============
    // ---- P0: top-30 + saturation on candidates; scatter dirty1 ----
    {
        const unsigned FULL = 0xffffffffu;
        float jump = *jumpp;
        for (int t = wgid; t < n; t += NWARPS) {
            int p = g_cand[t];
            int b = p >> 8, hw = p & 255;
            float v[16]; unsigned u[16];
            #pragma unroll
            for (int j = 0; j < 16; j++) {
                int c = lane + 32*j;
                float xv = (c < CIN) ? x[((size_t)b*CIN + c)*(HIN*WIN) + hw] : 0.f;
                v[j] = xv;
                u[j] = (c < CIN) ? __float_as_uint(fabsf(xv)) : 0u;
            }
            unsigned T = 0;
            for (int bit = 31; bit >= 0; bit--) {
                unsigned cand = T | (1u << bit);
                int cl = 0;
                #pragma unroll
                for (int j = 0; j < 16; j++) cl += (u[j] >= cand);
                if (warp_sum(cl) >= KTOP) T = cand;
            }
            int mg = 0;
            #pragma unroll
            for (int j = 0; j < 16; j++) mg += (u[j] > T);
            int need = KTOP - warp_sum(mg);
            int cnt_out = 0, base_tie = 0;
            unsigned lmask = (1u << lane) - 1u;
            #pragma unroll
            for (int j = 0; j < 16; j++) {
                int c = lane + 32*j;
                bool inr = (c < CIN);
                bool gt  = inr && (u[j] > T);
                bool eq  = inr && (u[j] == T);
                unsigned beq = __ballot_sync(FULL, eq);
                int tpre = base_tie + __popc(beq & lmask);
                base_tie += __popc(beq);
                bool keep = gt || (eq && tpre < need);
                float s = 0.f;
                if (keep) {
                    float r = v[j] / g_l1[c];
                    s = 0.5f * (sgnf(r - jump) + sgnf(r + jump));
                }
                bool emit = keep && (s != 0.f);
                unsigned be = __ballot_sync(FULL, emit);
                int pos = cnt_out + __popc(be & lmask);
                if (emit) {
                    __stcg(&g_chid[p*KTOP + pos], c);
                    __stcg(&g_qval[p*KTOP + pos], s * g_l1[c]);
                }
                cnt_out += __popc(be);
            }
            if (cnt_out > 0) {
                if (lane == 0) __stcg(&g_cnt[p], cnt_out);
                int ih = (p >> 4) & 15, iw = p & 15;
                if (lane < 16) {
                    int kh = lane >> 2, kw = lane & 3;
                    int idx = (b*O1 + 2*ih + kh)*O1 + (2*iw + kw);
                    if (atomicExch(&g_dirty1[idx], 1) == 0) {
                        int t1 = atomicAdd(&g_n1, 1);
                        __stcg(&g_list1[t1], idx);
                    }
                }
            }
        }
    }
    grid_bar(0);

    // ---- P1: conv1 delta at dirty1; scatter dirty2 ----
    {
        int n1 = __ldcg(&g_n1);
        for (int t = wgid; t < n1; t += NWARPS) {
            int idx = __ldcg(&g_list1[t]);
            int b = idx / (O1*O1), rem = idx % (O1*O1);
            int oh = rem / O1, ow = rem % O1;
            float acc[10];
            #pragma unroll
            for (int k = 0; k < 10; k++) acc[k] = 0.f;
            for (int kh = (oh & 1); kh < 4; kh += 2) {
                int dh = oh - kh; if (dh < 0 || dh > 30) continue;
                int ih = dh >> 1;
                for (int kw = (ow & 1); kw < 4; kw += 2) {
                    int dw = ow - kw; if (dw < 0 || dw > 30) continue;
                    int iw = dw >> 1;
                    int p = (b*16 + ih)*16 + iw;
                    int nz = __ldcg(&g_cnt[p]);
                    for (int e = 0; e < nz; e++) {
                        int c = __ldcg(&g_chid[p*KTOP + e]);
                        float qv = __ldcg(&g_qval[p*KTOP + e]);
                        const float* wp = w1 + (size_t)c*(C1*16) + kh*4 + kw;
                        #pragma unroll
                        for (int k = 0; k < 10; k++) {
                            int co = lane + 32*k;
                            if (co < C1) acc[k] += qv * wp[co*16];
                        }
                    }
                }
            }
            #pragma unroll
            for (int k = 0; k < 10; k++) {
                int co = lane + 32*k;
                if (co < C1) {
                    float bb = b1[co];
                    float d = fmaxf(bb + acc[k], 0.f) - fmaxf(bb, 0.f);
                    __stcg(&g_delta1[(((size_t)b*C1 + co)*O1 + oh)*O1 + ow], d);
                }
            }
            if (lane < 9) {
                int kh = lane / 3, kw = lane % 3;
                int idx2 = (b*O2 + oh + kh)*O2 + (ow + kw);
                if (atomicExch(&g_dirty2[idx2], 1) == 0) {
                    int t2 = atomicAdd(&g_n2, 1);
                    __stcg(&g_list2[t2], idx2);
                }
            }
        }
    }
    grid_bar(1);

    // ---- P2: conv2 delta at dirty2; scatter dirty3 ----
    {
        int n2 = __ldcg(&g_n2);
        for (int t = wgid; t < n2; t += NWARPS) {
            int idx = __ldcg(&g_list2[t]);
            int b = idx / (O2*O2), rem = idx % (O2*O2);
            int oh = rem / O2, ow = rem % O2;
            float acc[4] = {0.f,0.f,0.f,0.f};
            for (int kh = 0; kh < 3; kh++) {
                int q = oh - kh; if (q < 0 || q > 33) continue;
                for (int kw = 0; kw < 3; kw++) {
                    int r = ow - kw; if (r < 0 || r > 33) continue;
                    if (!__ldcg(&g_dirty1[(b*O1 + q)*O1 + r])) continue;
                    const float* dp = g_delta1 + (size_t)b*C1*O1*O1 + q*O1 + r;
                    const float* wb = w2 + kh*3 + kw;
                    for (int ci = 0; ci < C1; ci++) {
                        float dv = __ldcg(&dp[(size_t)ci*O1*O1]);
                        const float* wp = wb + (size_t)ci*(C2*9);
                        #pragma unroll
                        for (int k = 0; k < 4; k++) {
                            int co = lane + 32*k;
                            if (co < C2) acc[k] += dv * wp[co*9];
                        }
                    }
                }
            }
            int clh = cls36(oh), clw = cls36(ow);
            #pragma unroll
            for (int k = 0; k < 4; k++) {
                int co = lane + 32*k;
                if (co < C2) {
                    float pre = g_base2cls[(clh*5 + clw)*C2 + co];
                    float d = fmaxf(pre + acc[k], 0.f) - fmaxf(pre, 0.f);
                    __stcg(&g_delta2[(((size_t)b*C2 + co)*O2 + oh)*O2 + ow], d);
                }
            }
            if (lane < 9) {
                int kh = lane / 3, kw = lane % 3;
                __stcg(&g_dirty3[(b*O3 + oh + kh)*O3 + (ow + kw)], 1);
            }
        }
    }
    grid_bar(2);

    // ---- P3: output = crop(relu(base3 + conv3(delta2))) ----
    {
        const int TOT4 = BATCH*C3*32*32/4;     // 98304 float4
        #pragma unroll
        for (int t = 0; t < 2; t++) {
            int i4 = gid + t*NTHREADS;
            if (i4 >= TOT4) break;
            int xg4 = i4 & 7;
            int yg  = (i4 >> 3) & 31;
            int co  = (i4 >> 8) % 3;
            int b   = i4 / 768;
            int oh  = yg + 3;
            int ow0 = xg4*4 + 3;
            float r[4]; int dirty = 0;
            #pragma unroll
            for (int j = 0; j < 4; j++) {
                r[j] = g_base3[(co*O3 + oh)*O3 + ow0 + j];
                dirty |= __ldcg(&g_dirty3[(b*O3 + oh)*O3 + ow0 + j]);
            }
            if (dirty) {
                #pragma unroll
                for (int j = 0; j < 4; j++) {
                    int ow = ow0 + j;
                    if (!__ldcg(&g_dirty3[(b*O3 + oh)*O3 + ow])) continue;
                    for (int kh = 0; kh < 3; kh++) {
                        int q = oh - kh;
                        for (int kw = 0; kw < 3; kw++) {
                            int rr = ow - kw;
                            if (!__ldcg(&g_dirty2[(b*O2 + q)*O2 + rr])) continue;
                            for (int ci = 0; ci < C2; ci++)
                                r[j] += __ldcg(&g_delta2[(((size_t)b*C2 + ci)*O2 + q)*O2 + rr])
                                        * __ldg(&w3[((ci*3 + co)*3 + kh)*3 + kw]);
                        }
                    }
                }
            }
            float4 o4 = {fmaxf(r[0],0.f), fmaxf(r[1],0.f), fmaxf(r[2],0.f), fmaxf(r[3],0.f)};
            ((float4*)out)[i4] = o4;
        }
    }
}

// ---------------- launch ----------------
extern "C" void kernel_launch(void* const* d_in, const int* in_sizes, int n_in,
                              void* d_out, int out_size) {
    const float* x    = (const float*)d_in[0];
    const float* phi  = (const float*)d_in[1];
    const float* jump = (const float*)d_in[2];
    const float* w1   = (const float*)d_in[3];
    const float* b1   = (const float*)d_in[4];
    const float* w2   = (const float*)d_in[5];
    const float* b2   = (const float*)d_in[6];
    const float* w3   = (const float*)d_in[7];
    const float* b3   = (const float*)d_in[8];
    float* out = (float*)d_out;
    int D = in_sizes[1] / CIN;   // 192

    k_fused<<<1038, NT>>>((const float4*)x, phi, jump, D, w2, b1, b2, w3, b3);
    k_tail<<<NB, NT>>>(x, jump, w1, b1, w2, w3, out);
    (void)n_in; (void)out_size;
}

// round 12
// speedup vs baseline: 1.9153x; 1.4972x over previous
#include <cuda_runtime.h>

// ---------------- problem constants ----------------
#define BATCH 128
#define CIN   500
#define HIN   16
#define WIN   16
#define NPIX  (BATCH*HIN*WIN)     // 32768
#define KTOP  30

#define C1 300
#define O1 34
#define C2 100
#define O2 36
#define C3 3
#define O3 38

// k_tail: 296 blocks x 256 threads (148 SMs x 2, co-resident)
#define NB 296
#define NT 256
#define NTHREADS (NB*NT)          // 75776
#define NWARPS (NTHREADS/32)      // 2368

#define FLAG0 42                  // first flag block
#define NFB 1000                  // flag blocks
#define NFT (NFB*NT)              // 256000 flag threads
#define N4 (BATCH*CIN*HIN*WIN/4)  // 4,096,000 float4 = 16 * NFT exactly

// ---------------- static device scratch (zero at module load; self-cleaned) --
__device__ float g_l1[CIN];
__device__ float g_thr[CIN];
__device__ int   g_flagd[NPIX];
__device__ int   g_cand[NPIX];
__device__ int   g_ncand;
__device__ int   g_cnt[NPIX];
__device__ int   g_chid[NPIX*KTOP];
__device__ float g_qval[NPIX*KTOP];

__device__ int   g_dirty1[BATCH*O1*O1];
__device__ int   g_dirty2[BATCH*O2*O2];
__device__ int   g_dirty3[BATCH*O3*O3];
__device__ int   g_list1[BATCH*O1*O1];
__device__ int   g_list2[BATCH*O2*O2];
__device__ int   g_n1, g_n2;

__device__ float g_delta1[BATCH*C1*O1*O1];
__device__ float g_delta2[BATCH*C2*O2*O2];

__device__ float g_base2cls[25*C2];
__device__ float g_base3[C3*O3*O3];

__device__ int g_ready;           // 16 (thr blocks) + 16 (cleanup block) = 32
__device__ int g_b2_ready;        // 25 base2cls blocks
__device__ unsigned g_bar[4];     // packed count[0:12)/gen[12:32), monotonic

// ---------------- helpers ----------------
__device__ __forceinline__ float sgnf(float a) {
    return (float)((a > 0.f) - (a < 0.f));
}
__device__ __forceinline__ int warp_sum(int v) {
    #pragma unroll
    for (int o = 16; o > 0; o >>= 1) v += __shfl_xor_sync(0xffffffffu, v, o);
    return v;
}
__device__ __forceinline__ int cls36(int q) {
    return (q == 0) ? 0 : (q == 1) ? 1 : (q <= 33) ? 2 : (q == 34) ? 3 : 4;
}
__device__ __forceinline__ void grid_bar(int slot) {
    __syncthreads();
    if (threadIdx.x == 0) {
        __threadfence();
        unsigned old = atomicAdd(&g_bar[slot], 1u);
        unsigned gen0 = old >> 12;
        if ((old & 0xFFFu) == (unsigned)(NB - 1)) {
            atomicAdd(&g_bar[slot], (1u << 12) - (unsigned)NB);
        } else {
            while (((*(volatile unsigned*)&g_bar[slot]) >> 12) == gen0)
                __nanosleep(64);
        }
        __threadfence();
    }
    __syncthreads();
}
__device__ __forceinline__ void block_wait_ge(volatile int* flag, int val) {
    if (threadIdx.x == 0) {
        while (*flag < val) __nanosleep(64);
    }
    __syncthreads();
    __threadfence();
}

// ================= K1: fused — cleanup/thr/base2cls/base3 + flag stream =====
// blocks 0..15  : thr/l1 (add 1 to g_ready), then base3 row
// blocks 16..40 : base2cls 4 co each (add 1 to g_b2_ready); 16..37 also base3 row
// block  41     : cleanup prev-call scratch + reset counters (add 16 to g_ready)
// blocks 42..1041: flag stream over x (prefetch x, spin on g_ready==32)
__global__ __launch_bounds__(256, 5) void k_fused(
    const float4* __restrict__ x4,
    const float*  __restrict__ phi, const float* __restrict__ jumpp, int D,
    const float*  __restrict__ w2,  const float* __restrict__ b1,
    const float*  __restrict__ b2,  const float* __restrict__ w3,
    const float*  __restrict__ b3)
{
    __shared__ float s_buf[5200];   // 20.8 KB, unioned across phases
    __shared__ float s_W[36];
    int tid = threadIdx.x, bid = blockIdx.x;

    if (bid >= FLAG0) {
        // ---------------- flag stream ----------------
        int ft = (bid - FLAG0) * NT + tid;        // 0..255999
        // prefetch first batch BEFORE waiting for ready
        float4 v[8];
        #pragma unroll
        for (int k = 0; k < 8; k++) v[k] = x4[ft + k*NFT];
        block_wait_ge(&g_ready, 32);
        for (int i = tid; i < CIN; i += NT) s_buf[i] = __ldcg(&g_thr[i]);
        __syncthreads();
        #pragma unroll
        for (int half = 0; half < 2; half++) {
            if (half == 1) {
                #pragma unroll
                for (int k = 0; k < 8; k++) v[k] = x4[ft + (8 + k)*NFT];
            }
            #pragma unroll
            for (int k = 0; k < 8; k++) {
                int i = ft + (half*8 + k)*NFT;
                int ehw = i >> 6;
                int c = ehw % CIN;
                float th = s_buf[c];
                if (fabsf(v[k].x) >= th || fabsf(v[k].y) >= th ||
                    fabsf(v[k].z) >= th || fabsf(v[k].w) >= th) {
                    int b = ehw / CIN;
                    int pix = b*(HIN*WIN) + ((i*4) & (HIN*WIN-1));
                    if (atomicExch(&g_flagd[pix], 1) == 0) {
                        int t0 = atomicAdd(&g_ncand, 1);
                        g_cand[t0] = pix;
                    }
                }
            }
        }
        return;
    }

    // ---------------- producers (bid < 42) ----------------
    if (bid < 16) {
        // thr/l1 for channels bid*32 .. bid*32+31
        int lane = tid & 31, w = tid >> 5;        // 8 warps
        int c = bid*32 + lane;
        float s = 0.f;
        if (c < CIN) {
            if (D == 192) {
                int d0 = w * 24;
                #pragma unroll
                for (int k = 0; k < 24; k++)
                    s += fabsf(__ldg(&phi[(d0 + k)*CIN + c]));
            } else {
                int chunk = (D + 7) >> 3;
                int d0 = w*chunk, d1e = min(D, d0 + chunk);
                for (int d = d0; d < d1e; d++) s += fabsf(phi[d*CIN + c]);
            }
        }
        s_buf[w*32 + lane] = s;
        __syncthreads();
        if (tid < 32 && bid*32 + tid < CIN) {
            float t = 1e-12f;
            #pragma unroll
            for (int k = 0; k < 8; k++) t += s_buf[k*32 + tid];
            __stcg(&g_l1[bid*32 + tid],  t);
            __stcg(&g_thr[bid*32 + tid], (*jumpp) * t);
            __threadfence();
        }
        __syncthreads();
        if (tid == 0) atomicAdd(&g_ready, 1);
    } else if (bid < 41) {
        // base2cls for co = (bid-16)*4 .. +3  (25 blocks, R8-proven scheme)
        int g = tid >> 6, j = tid & 63;
        int co = (bid - 16)*4 + g;
        float w9[9];
        #pragma unroll
        for (int k = 0; k < 9; k++) w9[k] = 0.f;
        #pragma unroll
        for (int it = 0; it < 5; it++) {
            int ci = j + it*64;
            bool ok = (ci < C1);
            float y = ok ? fmaxf(__ldg(&b1[ok ? ci : 0]), 0.f) : 0.f;
            const float* wp = w2 + (size_t)(ok ? ci : 0)*900 + co*9;
            #pragma unroll
            for (int k = 0; k < 9; k++) {
                float wv = ok ? __ldg(&wp[k]) : 0.f;
                w9[k] += y * wv;
            }
        }
        #pragma unroll
        for (int k = 0; k < 9; k++) s_buf[(g*64 + j)*9 + k] = w9[k];
        __syncthreads();
        if (j < 9) {
            float s = 0.f;
            #pragma unroll 8
            for (int jj = 0; jj < 64; jj++) s += s_buf[(g*64 + jj)*9 + j];
            s_W[g*9 + j] = s;
        }
        __syncthreads();
        if (tid < 100) {
            const int kmin[5] = {0,0,0,1,2}, kmax[5] = {0,1,2,2,2};
            int cls = tid % 25, gg = tid / 25;
            int cco = (bid - 16)*4 + gg;
            int ch = cls / 5, cw = cls % 5;
            float acc = __ldg(&b2[cco]);
            for (int kh = kmin[ch]; kh <= kmax[ch]; kh++)
                for (int kw = kmin[cw]; kw <= kmax[cw]; kw++)
                    acc += s_W[gg*9 + kh*3 + kw];
            __stcg(&g_base2cls[cls*C2 + cco], acc);
        }
        __threadfence();
        __syncthreads();
        if (tid == 0) atomicAdd(&g_b2_ready, 1);
        if (bid >= 38) return;                    // blocks 38..40: no base3 row
    } else {
        // bid == 41: cleanup of prev call's scratch (empty in practice)
        int n = g_ncand;
        for (int t = tid; t < n; t += NT) {
            int p = g_cand[t];
            __stcg(&g_flagd[p], 0);
            __stcg(&g_cnt[p], 0);
        }
        int n1 = g_n1;
        for (int t = tid; t < n1; t += NT)
            __stcg(&g_dirty1[g_list1[t]], 0);
        int n2 = g_n2;
        for (int t = tid; t < n2; t += NT) {
            int idx = g_list2[t];
            int b = idx / (O2*O2), rem = idx % (O2*O2);
            int oh = rem / O2, ow = rem % O2;
            __stcg(&g_dirty2[idx], 0);
            for (int kh = 0; kh < 3; kh++)
                for (int kw = 0; kw < 3; kw++)
                    __stcg(&g_dirty3[(b*O3 + oh + kh)*O3 + (ow + kw)], 0);
        }
        __syncthreads();
        if (tid == 0) {
            __stcg(&g_ncand, 0); __stcg(&g_n1, 0); __stcg(&g_n2, 0);
            __threadfence();
            atomicAdd(&g_ready, 16);
        }
        return;
    }

    // ---------------- base3 row oh = bid (blocks 0..37) ----------------
    {
        float* s_b2r = s_buf;             // 2500
        float* s_w3  = s_buf + 2500;      // 2700
        __syncthreads();                  // producers done with s_buf
        for (int i = tid; i < C2*C3*9; i += NT) s_w3[i] = w3[i];
        block_wait_ge(&g_b2_ready, 25);
        for (int i = tid; i < 25*C2; i += NT) s_b2r[i] = fmaxf(__ldcg(&g_base2cls[i]), 0.f);
        __syncthreads();
        int oh = bid;
        if (tid < C3*O3) {
            int co = tid / O3, ow = tid % O3;
            float mh[3], mw[3]; int bh[3], bw[3];
            #pragma unroll
            for (int kh = 0; kh < 3; kh++) {
                int q = oh - kh; bool v = (q >= 0 && q <= 35);
                mh[kh] = v ? 1.f : 0.f; bh[kh] = v ? cls36(q)*5 : 0;
            }
            #pragma unroll
            for (int kw = 0; kw < 3; kw++) {
                int r = ow - kw; bool v = (r >= 0 && r <= 35);
                mw[kw] = v ? 1.f : 0.f; bw[kw] = v ? cls36(r) : 0;
            }
            float m[9]; int bi[9];
            #pragma unroll
            for (int kh = 0; kh < 3; kh++)
                #pragma unroll
                for (int kw = 0; kw < 3; kw++) {
                    m[kh*3+kw]  = mh[kh]*mw[kw];
                    bi[kh*3+kw] = (bh[kh]+bw[kw])*C2;
                }
            float acc = __ldg(&b3[co]);
            for (int ci = 0; ci < C2; ci++) {
                #pragma unroll
                for (int k = 0; k < 9; k++)
                    acc += m[k] * s_b2r[bi[k] + ci] * s_w3[(ci*3 + co)*9 + k];
            }
            __stcg(&g_base3[(co*O3 + oh)*O3 + ow], acc);
        }
    }
}

// ================= K2: tail — fast path (ncand==0) or barriered general =====
__global__ __launch_bounds__(NT, 2) void k_tail(
    const float* __restrict__ x,
    const float* __restrict__ jumpp,
    const float* __restrict__ w1,
    const float* __restrict__ b1,
    const float* __restrict__ w2,
    const float* __restrict__ w3,
    float* __restrict__ out)
{
    const int tid  = threadIdx.x;
    const int gid  = blockIdx.x * NT + tid;
    const int lane = tid & 31;
    const int wgid = gid >> 5;

    if (gid == 0) { g_ready = 0; g_b2_ready = 0; }   // safe: kernel ordering

    // g_ncand finalized by k_fused before this kernel: uniform across grid.
    const int n = __ldcg(&g_ncand);

    if (n == 0) {
        // ======== FAST PATH: out = relu(base3 crop), batch-broadcast =========
        const int TOT4 = BATCH*C3*32*32/4;     // 98304 float4
        #pragma unroll
        for (int t = 0; t < 2; t++) {
            int i4 = gid + t*NTHREADS;
            if (i4 >= TOT4) break;
            int xg4 = i4 & 7;
            int yg  = (i4 >> 3) & 31;
            int co  = (i4 >> 8) % 3;
            int oh  = yg + 3;
            int ow0 = xg4*4 + 3;
            float4 o4;
            o4.x = fmaxf(__ldcg(&g_base3[(co*O3 + oh)*O3 + ow0 + 0]), 0.f);
            o4.y = fmaxf(__ldcg(&g_base3[(co*O3 + oh)*O3 + ow0 + 1]), 0.f);
            o4.z = fmaxf(__ldcg(&g_base3[(co*O3 + oh)*O3 + ow0 + 2]), 0.f);
            o4.w = fmaxf(__ldcg(&g_base3[(co*O3 + oh)*O3 + ow0 + 3]), 0.f);
            ((float4*)out)[i4] = o4;
        }
        return;
    }

    // ======== GENERAL PATH (n > 0): full sparse-delta pipeline ===============
    {
        const unsigned FULL = 0xffffffffu;
        float jump = *jumpp;
        for (int t = wgid; t < n; t += NWARPS) {
            int p = g_cand[t];
            int b = p >> 8, hw = p & 255;
            float v[16]; unsigned u[16];
            #pragma unroll
            for (int j = 0; j < 16; j++) {
                int c = lane + 32*j;
                float xv = (c < CIN) ? x[((size_t)b*CIN + c)*(HIN*WIN) + hw] : 0.f;
                v[j] = xv;
                u[j] = (c < CIN) ? __float_as_uint(fabsf(xv)) : 0u;
            }
            unsigned T = 0;
            for (int bit = 31; bit >= 0; bit--) {
                unsigned cand = T | (1u << bit);
                int cl = 0;
                #pragma unroll
                for (int j = 0; j < 16; j++) cl += (u[j] >= cand);
                if (warp_sum(cl) >= KTOP) T = cand;
            }
            int mg = 0;
            #pragma unroll
            for (int j = 0; j < 16; j++) mg += (u[j] > T);
            int need = KTOP - warp_sum(mg);
            int cnt_out = 0, base_tie = 0;
            unsigned lmask = (1u << lane) - 1u;
            #pragma unroll
            for (int j = 0; j < 16; j++) {
                int c = lane + 32*j;
                bool inr = (c < CIN);
                bool gt  = inr && (u[j] > T);
                bool eq  = inr && (u[j] == T);
                unsigned beq = __ballot_sync(FULL, eq);
                int tpre = base_tie + __popc(beq & lmask);
                base_tie += __popc(beq);
                bool keep = gt || (eq && tpre < need);
                float s = 0.f;
                if (keep) {
                    float r = v[j] / g_l1[c];
                    s = 0.5f * (sgnf(r - jump) + sgnf(r + jump));
                }
                bool emit = keep && (s != 0.f);
                unsigned be = __ballot_sync(FULL, emit);
                int pos = cnt_out + __popc(be & lmask);
                if (emit) {
                    __stcg(&g_chid[p*KTOP + pos], c);
                    __stcg(&g_qval[p*KTOP + pos], s * g_l1[c]);
                }
                cnt_out += __popc(be);
            }
            if (cnt_out > 0) {
                if (lane == 0) __stcg(&g_cnt[p], cnt_out);
                int ih = (p >> 4) & 15, iw = p & 15;
                if (lane < 16) {
                    int kh = lane >> 2, kw = lane & 3;
                    int idx = (b*O1 + 2*ih + kh)*O1 + (2*iw + kw);
                    if (atomicExch(&g_dirty1[idx], 1) == 0) {
                        int t1 = atomicAdd(&g_n1, 1);
                        __stcg(&g_list1[t1], idx);
                    }
                }
            }
        }
    }
    grid_bar(0);

    {
        int n1 = __ldcg(&g_n1);
        for (int t = wgid; t < n1; t += NWARPS) {
            int idx = __ldcg(&g_list1[t]);
            int b = idx / (O1*O1), rem = idx % (O1*O1);
            int oh = rem / O1, ow = rem % O1;
            float acc[10];
            #pragma unroll
            for (int k = 0; k < 10; k++) acc[k] = 0.f;
            for (int kh = (oh & 1); kh < 4; kh += 2) {
                int dh = oh - kh; if (dh < 0 || dh > 30) continue;
                int ih = dh >> 1;
                for (int kw = (ow & 1); kw < 4; kw += 2) {
                    int dw = ow - kw; if (dw < 0 || dw > 30) continue;
                    int iw = dw >> 1;
                    int p = (b*16 + ih)*16 + iw;
                    int nz = __ldcg(&g_cnt[p]);
                    for (int e = 0; e < nz; e++) {
                        int c = __ldcg(&g_chid[p*KTOP + e]);
                        float qv = __ldcg(&g_qval[p*KTOP + e]);
                        const float* wp = w1 + (size_t)c*(C1*16) + kh*4 + kw;
                        #pragma unroll
                        for (int k = 0; k < 10; k++) {
                            int co = lane + 32*k;
                            if (co < C1) acc[k] += qv * wp[co*16];
                        }
                    }
                }
            }
            #pragma unroll
            for (int k = 0; k < 10; k++) {
                int co = lane + 32*k;
                if (co < C1) {
                    float bb = b1[co];
                    float d = fmaxf(bb + acc[k], 0.f) - fmaxf(bb, 0.f);
                    __stcg(&g_delta1[(((size_t)b*C1 + co)*O1 + oh)*O1 + ow], d);
                }
            }
            if (lane < 9) {
                int kh = lane / 3, kw = lane % 3;
                int idx2 = (b*O2 + oh + kh)*O2 + (ow + kw);
                if (atomicExch(&g_dirty2[idx2], 1) == 0) {
                    int t2 = atomicAdd(&g_n2, 1);
                    __stcg(&g_list2[t2], idx2);
                }
            }
        }
    }
    grid_bar(1);

    {
        int n2 = __ldcg(&g_n2);
        for (int t = wgid; t < n2; t += NWARPS) {
            int idx = __ldcg(&g_list2[t]);
            int b = idx / (O2*O2), rem = idx % (O2*O2);
            int oh = rem / O2, ow = rem % O2;
            float acc[4] = {0.f,0.f,0.f,0.f};
            for (int kh = 0; kh < 3; kh++) {
                int q = oh - kh; if (q < 0 || q > 33) continue;
                for (int kw = 0; kw < 3; kw++) {
                    int r = ow - kw; if (r < 0 || r > 33) continue;
                    if (!__ldcg(&g_dirty1[(b*O1 + q)*O1 + r])) continue;
                    const float* dp = g_delta1 + (size_t)b*C1*O1*O1 + q*O1 + r;
                    const float* wb = w2 + kh*3 + kw;
                    for (int ci = 0; ci < C1; ci++) {
                        float dv = __ldcg(&dp[(size_t)ci*O1*O1]);
                        const float* wp = wb + (size_t)ci*(C2*9);
                        #pragma unroll
                        for (int k = 0; k < 4; k++) {
                            int co = lane + 32*k;
                            if (co < C2) acc[k] += dv * wp[co*9];
                        }
                    }
                }
            }
            int clh = cls36(oh), clw = cls36(ow);
            #pragma unroll
            for (int k = 0; k < 4; k++) {
                int co = lane + 32*k;
                if (co < C2) {
                    float pre = g_base2cls[(clh*5 + clw)*C2 + co];
                    float d = fmaxf(pre + acc[k], 0.f) - fmaxf(pre, 0.f);
                    __stcg(&g_delta2[(((size_t)b*C2 + co)*O2 + oh)*O2 + ow], d);
                }
            }
            if (lane < 9) {
                int kh = lane / 3, kw = lane % 3;
                __stcg(&g_dirty3[(b*O3 + oh + kh)*O3 + (ow + kw)], 1);
            }
        }
    }
    grid_bar(2);

    {
        const int TOT4 = BATCH*C3*32*32/4;     // 98304 float4
        #pragma unroll
        for (int t = 0; t < 2; t++) {
            int i4 = gid + t*NTHREADS;
            if (i4 >= TOT4) break;
            int xg4 = i4 & 7;
            int yg  = (i4 >> 3) & 31;
            int co  = (i4 >> 8) % 3;
            int b   = i4 / 768;
            int oh  = yg + 3;
            int ow0 = xg4*4 + 3;
            float r[4]; int dirty = 0;
            #pragma unroll
            for (int j = 0; j < 4; j++) {
                r[j] = g_base3[(co*O3 + oh)*O3 + ow0 + j];
                dirty |= __ldcg(&g_dirty3[(b*O3 + oh)*O3 + ow0 + j]);
            }
            if (dirty) {
                #pragma unroll
                for (int j = 0; j < 4; j++) {
                    int ow = ow0 + j;
                    if (!__ldcg(&g_dirty3[(b*O3 + oh)*O3 + ow])) continue;
                    for (int kh = 0; kh < 3; kh++) {
                        int q = oh - kh;
                        for (int kw = 0; kw < 3; kw++) {
                            int rr = ow - kw;
                            if (!__ldcg(&g_dirty2[(b*O2 + q)*O2 + rr])) continue;
                            for (int ci = 0; ci < C2; ci++)
                                r[j] += __ldcg(&g_delta2[(((size_t)b*C2 + ci)*O2 + q)*O2 + rr])
                                        * __ldg(&w3[((ci*3 + co)*3 + kh)*3 + kw]);
                        }
                    }
                }
            }
            float4 o4 = {fmaxf(r[0],0.f), fmaxf(r[1],0.f), fmaxf(r[2],0.f), fmaxf(r[3],0.f)};
            ((float4*)out)[i4] = o4;
        }
    }
}

// ---------------- launch ----------------
extern "C" void kernel_launch(void* const* d_in, const int* in_sizes, int n_in,
                              void* d_out, int out_size) {
    const float* x    = (const float*)d_in[0];
    const float* phi  = (const float*)d_in[1];
    const float* jump = (const float*)d_in[2];
    const float* w1   = (const float*)d_in[3];
    const float* b1   = (const float*)d_in[4];
    const float* w2   = (const float*)d_in[5];
    const float* b2   = (const float*)d_in[6];
    const float* w3   = (const float*)d_in[7];
    const float* b3   = (const float*)d_in[8];
    float* out = (float*)d_out;
    int D = in_sizes[1] / CIN;   // 192

    k_fused<<<FLAG0 + NFB, NT>>>((const float4*)x, phi, jump, D, w2, b1, b2, w3, b3);
    k_tail<<<NB, NT>>>(x, jump, w1, b1, w2, w3, out);
    (void)n_in; (void)out_size;
}